// round 13
// baseline (speedup 1.0000x reference)
#include <cuda_runtime.h>

#define HH 512
#define WW 512
#define NPIX (HH*WW)
#define BSZ 64
#define THREADS 256
#define NGROUPS 4
#define GROUP_STRIDE (THREADS * 4)            // 1024 pixels between groups
#define BLOCK_PIX (THREADS * 4 * NGROUPS)     // 4096 pixels per block

__global__ __launch_bounds__(THREADS, 6) void uv_transform_kernel(
    const float* __restrict__ depth,
    const float* __restrict__ R0g,
    const float* __restrict__ t0g,
    const float* __restrict__ R1g,
    const float* __restrict__ t1g,
    const float* __restrict__ Kg,
    float* __restrict__ uv_out,
    float* __restrict__ d_out)
{
    const int b = blockIdx.y;
    // NGROUPS dense 4-pixel groups per thread, GROUP_STRIDE apart. Each warp
    // instruction covers a dense 512B span (lane stride 16B).
    const int p0 = blockIdx.x * BLOCK_PIX + threadIdx.x * 4;

    // Front-batch ALL depth loads (MLP=4) before the constant prologue.
    const float* dptr = depth + (size_t)b * NPIX + p0;
    float4 dep[NGROUPS];
    #pragma unroll
    for (int g = 0; g < NGROUPS; g++)
        dep[g] = *reinterpret_cast<const float4*>(dptr + g * GROUP_STRIDE);

    // ---- warp-local per-batch constant computation (every warp, no barrier) ----
    // Lane i (i<9) owns matrix entry (c,d) = (i/3, i%3); shuffle algebra.
    const int lane = threadIdx.x & 31;
    const int c = (lane / 3) % 3;
    const int d = lane % 3;
    const unsigned FM = 0xFFFFFFFFu;

    float r0v = 0.f, r1v = 0.f, kv = 0.f, t0v = 0.f, t1v = 0.f;
    if (lane < 9) {
        r0v = R0g[b * 9 + lane];
        r1v = R1g[b * 9 + lane];
        kv  = Kg[lane];
    }
    if (lane < 3) {
        t0v = t0g[b * 3 + lane];
        t1v = t1g[b * 3 + lane];
    }

    // M(c,d) = sum_e R0[c,e] * R1[d,e]   (R0 @ R1^T)
    float Mv = 0.f;
    #pragma unroll
    for (int e = 0; e < 3; e++)
        Mv = fmaf(__shfl_sync(FM, r0v, 3 * c + e),
                  __shfl_sync(FM, r1v, 3 * d + e), Mv);

    // A(c,d) = sum_e M[c,e] * K[d,e]     (M @ K^T)
    float Av = 0.f;
    #pragma unroll
    for (int e = 0; e < 3; e++)
        Av = fmaf(__shfl_sync(FM, Mv, 3 * c + e),
                  __shfl_sync(FM, kv, 3 * d + e), Av);

    // cofactor of K at (c,d) via cyclic indexing (sign-correct)
    const int rr1 = (c + 1) % 3, rr2 = (c + 2) % 3;
    const int cc1 = (d + 1) % 3, cc2 = (d + 2) % 3;
    const float cofv =
        __shfl_sync(FM, kv, 3 * rr1 + cc1) * __shfl_sync(FM, kv, 3 * rr2 + cc2)
      - __shfl_sync(FM, kv, 3 * rr1 + cc2) * __shfl_sync(FM, kv, 3 * rr2 + cc1);

    // det = sum_e K[0,e] * cof(0,e)
    float det = 0.f;
    #pragma unroll
    for (int e = 0; e < 3; e++)
        det = fmaf(__shfl_sync(FM, kv, e), __shfl_sync(FM, cofv, e), det);
    const float rdet = 1.0f / det;

    // Ki(c,d) = cof(d,c) / det   (adjugate transpose)
    const float Kiv = __shfl_sync(FM, cofv, 3 * d + c) * rdet;

    // Bv(c,d) = sum_k Ki[k,c] * A[k,d]   (Ki^T @ A)
    float Bv = 0.f;
    #pragma unroll
    for (int k = 0; k < 3; k++)
        Bv = fmaf(__shfl_sync(FM, Kiv, 3 * k + c),
                  __shfl_sync(FM, Av, 3 * k + d), Bv);

    // biasv for lanes 0..2 (d = lane): t1 @ K^T - t0 @ A
    float biasv = 0.f;
    #pragma unroll
    for (int e = 0; e < 3; e++) {
        biasv = fmaf(__shfl_sync(FM, t1v, e),
                     __shfl_sync(FM, kv, 3 * d + e), biasv);
        biasv = fmaf(-__shfl_sync(FM, t0v, e),
                     __shfl_sync(FM, Av, 3 * e + d), biasv);
    }

    // Broadcast the 12 constants to all lanes (no smem, no barrier).
    const float B00 = __shfl_sync(FM, Bv, 0);
    const float B01 = __shfl_sync(FM, Bv, 1);
    const float B02 = __shfl_sync(FM, Bv, 2);
    const float B10 = __shfl_sync(FM, Bv, 3);
    const float B11 = __shfl_sync(FM, Bv, 4);
    const float B12 = __shfl_sync(FM, Bv, 5);
    const float B20 = __shfl_sync(FM, Bv, 6);
    const float B21 = __shfl_sync(FM, Bv, 7);
    const float B22 = __shfl_sync(FM, Bv, 8);
    const float b0  = __shfl_sync(FM, biasv, 0);
    const float b1  = __shfl_sync(FM, biasv, 1);
    const float b2  = __shfl_sync(FM, biasv, 2);

    // pixel coords: 4 consecutive pixels share a row; successive groups sit
    // exactly 2 rows apart (GROUP_STRIDE = 1024 = 2 * 512).
    const float row = (float)(p0 >> 9);
    const float col = (float)(p0 & 511);

    float gr0 = fmaf(col, B00, fmaf(row, B10, B20));
    float gr1 = fmaf(col, B01, fmaf(row, B11, B21));
    float gr2 = fmaf(col, B02, fmaf(row, B12, B22));
    const float dR0 = 2.0f * B10, dR1 = 2.0f * B11, dR2 = 2.0f * B12;

    float* uvp = uv_out + ((size_t)b * NPIX + p0) * 2;
    float* ddp = d_out + (size_t)b * NPIX + p0;

    #pragma unroll
    for (int g = 0; g < NGROUPS; g++) {
        const float dv[4] = {dep[g].x, dep[g].y, dep[g].z, dep[g].w};

        float r0 = gr0, r1 = gr1, r2 = gr2;
        float u[4], v[4], dd[4];
        #pragma unroll
        for (int i = 0; i < 4; i++) {
            const float u3 = fmaf(dv[i], r0, b0);
            const float v3 = fmaf(dv[i], r1, b1);
            const float w3 = fmaf(dv[i], r2, b2);
            dd[i] = w3;
            const float rcp = __frcp_rn(fmaxf(w3, 0.0f) + 1e-12f);
            u[i] = u3 * rcp;
            v[i] = v3 * rcp;
            r0 += B00; r1 += B01; r2 += B02;  // advance one column
        }

        // store this group immediately (keeps u/v/dd transient)
        float4 uvA, uvB, dq;
        uvA.x = u[0]; uvA.y = v[0]; uvA.z = u[1]; uvA.w = v[1];
        uvB.x = u[2]; uvB.y = v[2]; uvB.z = u[3]; uvB.w = v[3];
        dq.x = dd[0]; dq.y = dd[1]; dq.z = dd[2]; dq.w = dd[3];

        *reinterpret_cast<float4*>(uvp + g * (GROUP_STRIDE * 2))     = uvA;
        *reinterpret_cast<float4*>(uvp + g * (GROUP_STRIDE * 2) + 4) = uvB;
        *reinterpret_cast<float4*>(ddp + g * GROUP_STRIDE)           = dq;

        // advance two rows for the next group
        gr0 += dR0; gr1 += dR1; gr2 += dR2;
    }
}

extern "C" void kernel_launch(void* const* d_in, const int* in_sizes, int n_in,
                              void* d_out, int out_size)
{
    // metadata order: depth0, R0, t0, R1, t1, K, ray
    const float* depth = (const float*)d_in[0];
    const float* R0    = (const float*)d_in[1];
    const float* t0    = (const float*)d_in[2];
    const float* R1    = (const float*)d_in[3];
    const float* t1    = (const float*)d_in[4];
    const float* K     = (const float*)d_in[5];

    float* uv_out = (float*)d_out;                           // BS*N*2 floats
    float* dd_out = (float*)d_out + (size_t)BSZ * NPIX * 2;  // BS*N floats

    dim3 grid(NPIX / BLOCK_PIX, BSZ);
    uv_transform_kernel<<<grid, THREADS>>>(depth, R0, t0, R1, t1, K, uv_out, dd_out);
}

// round 14
// speedup vs baseline: 1.0307x; 1.0307x over previous
#include <cuda_runtime.h>

#define HH 512
#define WW 512
#define NPIX (HH*WW)
#define BSZ 64
#define THREADS 256
#define GROUP_STRIDE (THREADS * 4)        // 1024 pixels between a thread's two groups
#define BLOCK_PIX (THREADS * 8)           // 2048 pixels per block

__global__ __launch_bounds__(THREADS, 8) void uv_transform_kernel(
    const float* __restrict__ depth,
    const float* __restrict__ R0g,
    const float* __restrict__ t0g,
    const float* __restrict__ R1g,
    const float* __restrict__ t1g,
    const float* __restrict__ Kg,
    float* __restrict__ uv_out,
    float* __restrict__ d_out)
{
    const int b = blockIdx.y;
    // Two dense 4-pixel groups per thread, GROUP_STRIDE apart. Warp-level
    // footprint per instruction stays dense (lane stride 16B = 512B/warp).
    const int p0 = blockIdx.x * BLOCK_PIX + threadIdx.x * 4;

    // Front-batch BOTH depth loads (MLP=2) before the constant prologue:
    // independent of the constants, their DRAM latency hides the shuffles.
    const float* dptr = depth + (size_t)b * NPIX + p0;
    const float4 dep0 = *reinterpret_cast<const float4*>(dptr);
    const float4 dep1 = *reinterpret_cast<const float4*>(dptr + GROUP_STRIDE);

    // ---- warp-local per-batch constant computation (every warp, no barrier) ----
    // Lane i (i<9) owns matrix entry (c,d) = (i/3, i%3); shuffle algebra (R9 form).
    const int lane = threadIdx.x & 31;
    const int c = (lane / 3) % 3;
    const int d = lane % 3;
    const unsigned FM = 0xFFFFFFFFu;

    float r0v = 0.f, r1v = 0.f, kv = 0.f, t0v = 0.f, t1v = 0.f;
    if (lane < 9) {
        r0v = R0g[b * 9 + lane];
        r1v = R1g[b * 9 + lane];
        kv  = Kg[lane];
    }
    if (lane < 3) {
        t0v = t0g[b * 3 + lane];
        t1v = t1g[b * 3 + lane];
    }

    // M(c,d) = sum_e R0[c,e] * R1[d,e]   (R0 @ R1^T)
    float Mv = 0.f;
    #pragma unroll
    for (int e = 0; e < 3; e++)
        Mv = fmaf(__shfl_sync(FM, r0v, 3 * c + e),
                  __shfl_sync(FM, r1v, 3 * d + e), Mv);

    // A(c,d) = sum_e M[c,e] * K[d,e]     (M @ K^T)
    float Av = 0.f;
    #pragma unroll
    for (int e = 0; e < 3; e++)
        Av = fmaf(__shfl_sync(FM, Mv, 3 * c + e),
                  __shfl_sync(FM, kv, 3 * d + e), Av);

    // cofactor of K at (c,d) via cyclic indexing (sign-correct)
    const int rr1 = (c + 1) % 3, rr2 = (c + 2) % 3;
    const int cc1 = (d + 1) % 3, cc2 = (d + 2) % 3;
    const float cofv =
        __shfl_sync(FM, kv, 3 * rr1 + cc1) * __shfl_sync(FM, kv, 3 * rr2 + cc2)
      - __shfl_sync(FM, kv, 3 * rr1 + cc2) * __shfl_sync(FM, kv, 3 * rr2 + cc1);

    // det = sum_e K[0,e] * cof(0,e)
    float det = 0.f;
    #pragma unroll
    for (int e = 0; e < 3; e++)
        det = fmaf(__shfl_sync(FM, kv, e), __shfl_sync(FM, cofv, e), det);
    const float rdet = 1.0f / det;

    // Ki(c,d) = cof(d,c) / det   (adjugate transpose)
    const float Kiv = __shfl_sync(FM, cofv, 3 * d + c) * rdet;

    // Bv(c,d) = sum_k Ki[k,c] * A[k,d]   (Ki^T @ A)
    float Bv = 0.f;
    #pragma unroll
    for (int k = 0; k < 3; k++)
        Bv = fmaf(__shfl_sync(FM, Kiv, 3 * k + c),
                  __shfl_sync(FM, Av, 3 * k + d), Bv);

    // biasv for lanes 0..2 (d = lane): t1 @ K^T - t0 @ A
    float biasv = 0.f;
    #pragma unroll
    for (int e = 0; e < 3; e++) {
        biasv = fmaf(__shfl_sync(FM, t1v, e),
                     __shfl_sync(FM, kv, 3 * d + e), biasv);
        biasv = fmaf(-__shfl_sync(FM, t0v, e),
                     __shfl_sync(FM, Av, 3 * e + d), biasv);
    }

    // Broadcast the 12 constants to all lanes (no smem, no barrier).
    const float B00 = __shfl_sync(FM, Bv, 0);
    const float B01 = __shfl_sync(FM, Bv, 1);
    const float B02 = __shfl_sync(FM, Bv, 2);
    const float B10 = __shfl_sync(FM, Bv, 3);
    const float B11 = __shfl_sync(FM, Bv, 4);
    const float B12 = __shfl_sync(FM, Bv, 5);
    const float B20 = __shfl_sync(FM, Bv, 6);
    const float B21 = __shfl_sync(FM, Bv, 7);
    const float B22 = __shfl_sync(FM, Bv, 8);
    const float b0  = __shfl_sync(FM, biasv, 0);
    const float b1  = __shfl_sync(FM, biasv, 1);
    const float b2  = __shfl_sync(FM, biasv, 2);

    // pixel coords: 4 consecutive pixels share a row; group 1 sits exactly
    // 2 rows below group 0 (GROUP_STRIDE = 1024 = 2 * 512).
    const float row = (float)(p0 >> 9);
    const float col = (float)(p0 & 511);

    float gr0 = fmaf(col, B00, fmaf(row, B10, B20));
    float gr1 = fmaf(col, B01, fmaf(row, B11, B21));
    float gr2 = fmaf(col, B02, fmaf(row, B12, B22));

    float* uvp = uv_out + ((size_t)b * NPIX + p0) * 2;
    float* ddp = d_out + (size_t)b * NPIX + p0;

    #pragma unroll
    for (int g = 0; g < 2; g++) {
        const float4 dep = g ? dep1 : dep0;
        const float dv[4] = {dep.x, dep.y, dep.z, dep.w};

        float r0 = gr0, r1 = gr1, r2 = gr2;
        float u[4], v[4], dd[4];
        #pragma unroll
        for (int i = 0; i < 4; i++) {
            const float u3 = fmaf(dv[i], r0, b0);
            const float v3 = fmaf(dv[i], r1, b1);
            const float w3 = fmaf(dv[i], r2, b2);
            dd[i] = w3;
            const float rcp = __frcp_rn(fmaxf(w3, 0.0f) + 1e-12f);
            u[i] = u3 * rcp;
            v[i] = v3 * rcp;
            r0 += B00; r1 += B01; r2 += B02;  // advance one column
        }

        float4 uvA, uvB, dq;
        uvA.x = u[0]; uvA.y = v[0]; uvA.z = u[1]; uvA.w = v[1];
        uvB.x = u[2]; uvB.y = v[2]; uvB.z = u[3]; uvB.w = v[3];
        dq.x = dd[0]; dq.y = dd[1]; dq.z = dd[2]; dq.w = dd[3];

        *reinterpret_cast<float4*>(uvp + g * (GROUP_STRIDE * 2))     = uvA;
        *reinterpret_cast<float4*>(uvp + g * (GROUP_STRIDE * 2) + 4) = uvB;
        *reinterpret_cast<float4*>(ddp + g * GROUP_STRIDE)           = dq;

        // advance two rows for group 1
        gr0 += 2.0f * B10; gr1 += 2.0f * B11; gr2 += 2.0f * B12;
    }
}

extern "C" void kernel_launch(void* const* d_in, const int* in_sizes, int n_in,
                              void* d_out, int out_size)
{
    // metadata order: depth0, R0, t0, R1, t1, K, ray
    const float* depth = (const float*)d_in[0];
    const float* R0    = (const float*)d_in[1];
    const float* t0    = (const float*)d_in[2];
    const float* R1    = (const float*)d_in[3];
    const float* t1    = (const float*)d_in[4];
    const float* K     = (const float*)d_in[5];

    float* uv_out = (float*)d_out;                           // BS*N*2 floats
    float* dd_out = (float*)d_out + (size_t)BSZ * NPIX * 2;  // BS*N floats

    dim3 grid(NPIX / BLOCK_PIX, BSZ);
    uv_transform_kernel<<<grid, THREADS>>>(depth, R0, t0, R1, t1, K, uv_out, dd_out);
}

// round 15
// speedup vs baseline: 1.0358x; 1.0049x over previous
#include <cuda_runtime.h>

#define HH 512
#define WW 512
#define NPIX (HH*WW)
#define BSZ 64
#define THREADS 256
#define GROUP_STRIDE (THREADS * 4)        // 1024 pixels between a thread's two groups
#define BLOCK_PIX (THREADS * 8)           // 2048 pixels per block

__global__ __launch_bounds__(THREADS, 7) void uv_transform_kernel(
    const float* __restrict__ depth,
    const float* __restrict__ R0g,
    const float* __restrict__ t0g,
    const float* __restrict__ R1g,
    const float* __restrict__ t1g,
    const float* __restrict__ Kg,
    float* __restrict__ uv_out,
    float* __restrict__ d_out)
{
    const int b = blockIdx.y;
    // Two dense 4-pixel groups per thread, GROUP_STRIDE apart. Warp-level
    // footprint per instruction stays dense (lane stride 16B = 512B/warp).
    const int p0 = blockIdx.x * BLOCK_PIX + threadIdx.x * 4;

    // Front-batch BOTH depth loads (MLP=2) before the constant prologue:
    // independent of the constants, their DRAM latency hides the shuffles.
    const float* dptr = depth + (size_t)b * NPIX + p0;
    const float4 dep0 = *reinterpret_cast<const float4*>(dptr);
    const float4 dep1 = *reinterpret_cast<const float4*>(dptr + GROUP_STRIDE);

    // ---- warp-local per-batch constant computation (every warp, no barrier) ----
    // Lane i (i<9) owns matrix entry (c,d) = (i/3, i%3); shuffle algebra.
    const int lane = threadIdx.x & 31;
    const int c = (lane / 3) % 3;
    const int d = lane % 3;
    const unsigned FM = 0xFFFFFFFFu;

    float r0v = 0.f, r1v = 0.f, kv = 0.f, t0v = 0.f, t1v = 0.f;
    if (lane < 9) {
        r0v = R0g[b * 9 + lane];
        r1v = R1g[b * 9 + lane];
        kv  = Kg[lane];
    }
    if (lane < 3) {
        t0v = t0g[b * 3 + lane];
        t1v = t1g[b * 3 + lane];
    }

    // M(c,d) = sum_e R0[c,e] * R1[d,e]   (R0 @ R1^T)
    float Mv = 0.f;
    #pragma unroll
    for (int e = 0; e < 3; e++)
        Mv = fmaf(__shfl_sync(FM, r0v, 3 * c + e),
                  __shfl_sync(FM, r1v, 3 * d + e), Mv);

    // A(c,d) = sum_e M[c,e] * K[d,e]     (M @ K^T)
    float Av = 0.f;
    #pragma unroll
    for (int e = 0; e < 3; e++)
        Av = fmaf(__shfl_sync(FM, Mv, 3 * c + e),
                  __shfl_sync(FM, kv, 3 * d + e), Av);

    // cofactor of K at (c,d) via cyclic indexing (sign-correct)
    const int rr1 = (c + 1) % 3, rr2 = (c + 2) % 3;
    const int cc1 = (d + 1) % 3, cc2 = (d + 2) % 3;
    const float cofv =
        __shfl_sync(FM, kv, 3 * rr1 + cc1) * __shfl_sync(FM, kv, 3 * rr2 + cc2)
      - __shfl_sync(FM, kv, 3 * rr1 + cc2) * __shfl_sync(FM, kv, 3 * rr2 + cc1);

    // det = sum_e K[0,e] * cof(0,e)
    float det = 0.f;
    #pragma unroll
    for (int e = 0; e < 3; e++)
        det = fmaf(__shfl_sync(FM, kv, e), __shfl_sync(FM, cofv, e), det);
    const float rdet = 1.0f / det;

    // Ki(c,d) = cof(d,c) / det   (adjugate transpose)
    const float Kiv = __shfl_sync(FM, cofv, 3 * d + c) * rdet;

    // Bv(c,d) = sum_k Ki[k,c] * A[k,d]   (Ki^T @ A)
    float Bv = 0.f;
    #pragma unroll
    for (int k = 0; k < 3; k++)
        Bv = fmaf(__shfl_sync(FM, Kiv, 3 * k + c),
                  __shfl_sync(FM, Av, 3 * k + d), Bv);

    // biasv for lanes 0..2 (d = lane): t1 @ K^T - t0 @ A
    float biasv = 0.f;
    #pragma unroll
    for (int e = 0; e < 3; e++) {
        biasv = fmaf(__shfl_sync(FM, t1v, e),
                     __shfl_sync(FM, kv, 3 * d + e), biasv);
        biasv = fmaf(-__shfl_sync(FM, t0v, e),
                     __shfl_sync(FM, Av, 3 * e + d), biasv);
    }

    // Broadcast the 12 constants to all lanes (no smem, no barrier).
    const float B00 = __shfl_sync(FM, Bv, 0);
    const float B01 = __shfl_sync(FM, Bv, 1);
    const float B02 = __shfl_sync(FM, Bv, 2);
    const float B10 = __shfl_sync(FM, Bv, 3);
    const float B11 = __shfl_sync(FM, Bv, 4);
    const float B12 = __shfl_sync(FM, Bv, 5);
    const float B20 = __shfl_sync(FM, Bv, 6);
    const float B21 = __shfl_sync(FM, Bv, 7);
    const float B22 = __shfl_sync(FM, Bv, 8);
    const float b0  = __shfl_sync(FM, biasv, 0);
    const float b1  = __shfl_sync(FM, biasv, 1);
    const float b2  = __shfl_sync(FM, biasv, 2);

    // pixel coords: 4 consecutive pixels share a row; group 1 sits exactly
    // 2 rows below group 0 (GROUP_STRIDE = 1024 = 2 * 512).
    const float row = (float)(p0 >> 9);
    const float col = (float)(p0 & 511);

    float gr0 = fmaf(col, B00, fmaf(row, B10, B20));
    float gr1 = fmaf(col, B01, fmaf(row, B11, B21));
    float gr2 = fmaf(col, B02, fmaf(row, B12, B22));

    float* uvp = uv_out + ((size_t)b * NPIX + p0) * 2;
    float* ddp = d_out + (size_t)b * NPIX + p0;

    #pragma unroll
    for (int g = 0; g < 2; g++) {
        const float4 dep = g ? dep1 : dep0;
        const float dv[4] = {dep.x, dep.y, dep.z, dep.w};

        float r0 = gr0, r1 = gr1, r2 = gr2;
        float u[4], v[4], dd[4];
        #pragma unroll
        for (int i = 0; i < 4; i++) {
            const float u3 = fmaf(dv[i], r0, b0);
            const float v3 = fmaf(dv[i], r1, b1);
            const float w3 = fmaf(dv[i], r2, b2);
            dd[i] = w3;
            const float rcp = __frcp_rn(fmaxf(w3, 0.0f) + 1e-12f);
            u[i] = u3 * rcp;
            v[i] = v3 * rcp;
            r0 += B00; r1 += B01; r2 += B02;  // advance one column
        }

        float4 uvA, uvB, dq;
        uvA.x = u[0]; uvA.y = v[0]; uvA.z = u[1]; uvA.w = v[1];
        uvB.x = u[2]; uvB.y = v[2]; uvB.z = u[3]; uvB.w = v[3];
        dq.x = dd[0]; dq.y = dd[1]; dq.z = dd[2]; dq.w = dd[3];

        // Write-through stores: outputs are never re-read; avoid L2
        // dirty-line accumulation so writebacks don't burst against reads.
        __stwt(reinterpret_cast<float4*>(uvp + g * (GROUP_STRIDE * 2)), uvA);
        __stwt(reinterpret_cast<float4*>(uvp + g * (GROUP_STRIDE * 2) + 4), uvB);
        __stwt(reinterpret_cast<float4*>(ddp + g * GROUP_STRIDE), dq);

        // advance two rows for group 1
        gr0 += 2.0f * B10; gr1 += 2.0f * B11; gr2 += 2.0f * B12;
    }
}

extern "C" void kernel_launch(void* const* d_in, const int* in_sizes, int n_in,
                              void* d_out, int out_size)
{
    // metadata order: depth0, R0, t0, R1, t1, K, ray
    const float* depth = (const float*)d_in[0];
    const float* R0    = (const float*)d_in[1];
    const float* t0    = (const float*)d_in[2];
    const float* R1    = (const float*)d_in[3];
    const float* t1    = (const float*)d_in[4];
    const float* K     = (const float*)d_in[5];

    float* uv_out = (float*)d_out;                           // BS*N*2 floats
    float* dd_out = (float*)d_out + (size_t)BSZ * NPIX * 2;  // BS*N floats

    dim3 grid(NPIX / BLOCK_PIX, BSZ);
    uv_transform_kernel<<<grid, THREADS>>>(depth, R0, t0, R1, t1, K, uv_out, dd_out);
}